// round 16
// baseline (speedup 1.0000x reference)
#include <cuda_runtime.h>
#include <cuda_bf16.h>
#include <math.h>
#include <stdint.h>

// Fixed problem shapes
#define M_TOT 8192
#define NREL  64
#define D     128
#define TM    32            // m per tile -> 64 A rows (u rows 0..31, v rows 32..63)
#define THREADS 256
#define NBLK  296           // 2 blocks/SM x 148 SMs, all resident -> safe grid barrier
#define REG_LAMBDA 1e-5f

// ---------------- device scratch (zero-init at load; reset at end of each call) ----------------
__device__ int   g_cnt[NREL];
__device__ int4  g_bucket4[NREL * M_TOT];    // {m, h[m], pos[m], neg[m]}
__device__ float g_rsq[NREL];
__device__ float g_val[M_TOT];
__device__ unsigned int g_done;
__device__ unsigned int g_bar;
__device__ unsigned int g_tilectr;
// B fragments in mma.m16n8k16 register layout:
// g_bfrag[rel*4096 + ks*512 + nt*32 + lane] = {b0_hi, b1_hi, b0_lo, b1_lo}
__device__ uint4 g_bfrag[NREL * 8 * 16 * 32];

// ---------------- helpers ----------------
// packed 2-value bf16 split (rn rounding)
static __device__ __forceinline__ void split2(float x0, float x1, uint32_t& hi, uint32_t& lo) {
    asm("cvt.rn.bf16x2.f32 %0, %1, %2;" : "=r"(hi) : "f"(x1), "f"(x0));
    float h0 = __uint_as_float(hi << 16);
    float h1 = __uint_as_float(hi & 0xffff0000u);
    float l0 = x0 - h0;
    float l1 = x1 - h1;
    asm("cvt.rn.bf16x2.f32 %0, %1, %2;" : "=r"(lo) : "f"(l1), "f"(l0));
}

static __device__ __forceinline__ void mma_bf16(float c[4],
                                                uint32_t a0, uint32_t a1,
                                                uint32_t a2, uint32_t a3,
                                                uint32_t b0, uint32_t b1) {
    asm("mma.sync.aligned.m16n8k16.row.col.f32.bf16.bf16.f32 "
        "{%0,%1,%2,%3}, {%4,%5,%6,%7}, {%8,%9}, {%0,%1,%2,%3};"
        : "+f"(c[0]), "+f"(c[1]), "+f"(c[2]), "+f"(c[3])
        : "r"(a0), "r"(a1), "r"(a2), "r"(a3), "r"(b0), "r"(b1));
}

// ---------------- smem layout (dynamic ~99 KB) ----------------
#define ASTRIDE 264
#define OFF_AHI 0                          // 64 * 264 = 16896
#define OFF_ALO 16896                      // -> 33792
#define OFF_BSM 33792                      // 65536 B of B fragments -> 99328
#define OFF_RSH 99328                      // 512
#define OFF_SC  99840                      // 512 (128 floats: [p*64 + row])
#define OFF_REG 100352                     // 128 (32 floats)
#define OFF_MSH 100480                     // 128
#define OFF_SCNT 100608                    // 256
#define OFF_STP  100864                    // 65 ints
#define OFF_CTL  101136                    // {rel, start, cnt}
#define SMEM_SZ  101376

__global__ void __launch_bounds__(THREADS, 2) k_all(
    const int*   __restrict__ r,
    const int*   __restrict__ h,
    const int*   __restrict__ pos_t,
    const int*   __restrict__ neg_t,
    const float* __restrict__ ent,
    const float* __restrict__ rel_emb,
    const float* __restrict__ rel_w,
    float*       __restrict__ out)
{
    extern __shared__ char smem[];
    int b   = blockIdx.x;
    int tid = threadIdx.x;
    int w = tid >> 5, l = tid & 31;
    int g = w >> 1, p = w & 1;           // warp pair (rows), j-half
    int gid = l >> 2, tig = l & 3;

    // ================= Phase 1: scatter (blocks 0-31) / W fragments (32-159) =================
    if (b < 32) {
        int* scnt  = (int*)smem;
        int* sbase = scnt + NREL;
        int* scur  = sbase + NREL;
        if (tid < NREL) { scnt[tid] = 0; scur[tid] = 0; }
        __syncthreads();
        int m  = b * 256 + tid;
        int rl = r[m];
        int hm = h[m], pm = pos_t[m], nm = neg_t[m];
        atomicAdd(&scnt[rl], 1);
        __syncthreads();
        if (tid < NREL && scnt[tid] > 0) sbase[tid] = atomicAdd(&g_cnt[tid], scnt[tid]);
        __syncthreads();
        int pp = sbase[rl] + atomicAdd(&scur[rl], 1);
        g_bucket4[rl * M_TOT + pp] = make_int4(m, hm, pm, nm);
        if (b == 0) {
            for (int rel = w; rel < NREL; rel += 8) {
                const float4* re = (const float4*)(rel_emb + rel * D);
                float4 v = re[l];
                float s = v.x * v.x + v.y * v.y + v.z * v.z + v.w * v.w;
                #pragma unroll
                for (int o = 16; o; o >>= 1) s += __shfl_xor_sync(0xffffffffu, s, o);
                if (l == 0) g_rsq[rel] = s;
            }
        }
    } else if (b < 160) {
        // half-rel builder: 128 blocks, 32 KB stage (rows 64*half .. 64*half+63)
        int idx  = b - 32;
        int rel  = idx >> 1;
        int half = idx & 1;
        float* Wsh = (float*)smem;          // 64 x 128 f32 = 32 KB
        const float4* src = (const float4*)(rel_w + (size_t)rel * D * D + (size_t)(64 * half) * D);
        float4* dst = (float4*)Wsh;
        #pragma unroll
        for (int i = tid; i < 64 * D / 4; i += 256) dst[i] = src[i];   // coalesced
        __syncthreads();
        #pragma unroll
        for (int q = 0; q < 8; q++) {
            int e = half * 2048 + q * 256 + tid;   // global entry index within rel
            int lane = e & 31;
            int nt   = (e >> 5) & 15;
            int ks   = e >> 9;
            int gg = lane >> 2, tt = lane & 3;
            int j  = 8 * nt + gg;
            int lr = 16 * ks + 2 * tt - 64 * half; // local staged row
            uint32_t xh, xl, yh, yl;
            split2(Wsh[lr * D + j], Wsh[(lr + 1) * D + j], xh, xl);
            split2(Wsh[(lr + 8) * D + j], Wsh[(lr + 9) * D + j], yh, yl);
            g_bfrag[(size_t)rel * 4096 + e] = make_uint4(xh, yh, xl, yl);
        }
    }

    // ================= Grid barrier (all 296 blocks resident; volatile poll) =================
    __threadfence();
    __syncthreads();
    if (tid == 0) {
        atomicAdd(&g_bar, 1u);
        while (*(volatile unsigned int*)&g_bar < NBLK) __nanosleep(32);
    }
    __syncthreads();

    // ================= Phase 2: per-block plan + tile loop =================
    float* rsh   = (float*)(smem + OFF_RSH);
    float* sc    = (float*)(smem + OFF_SC);
    float* regsh = (float*)(smem + OFF_REG);
    int*   msh   = (int*)(smem + OFF_MSH);
    int*   scnt  = (int*)(smem + OFF_SCNT);
    int*   stp   = (int*)(smem + OFF_STP);

    if (tid < NREL) scnt[tid] = g_cnt[tid];
    __syncthreads();
    if (w == 0) {
        // warp-parallel tile-offset scan: lane l covers rels 2l, 2l+1
        int a0 = (scnt[2 * l] + TM - 1) / TM;
        int a1 = (scnt[2 * l + 1] + TM - 1) / TM;
        int s  = a0 + a1;
        int sum = s;
        #pragma unroll
        for (int off = 1; off < 32; off <<= 1) {
            int t = __shfl_up_sync(0xffffffffu, sum, off);
            if (l >= off) sum += t;
        }
        int excl = sum - s;
        stp[2 * l]     = excl;
        stp[2 * l + 1] = excl + a0;
        if (l == 31) stp[NREL] = sum;
    }
    __syncthreads();
    int ntiles = stp[NREL];

    uint32_t bsm_base = (uint32_t)__cvta_generic_to_shared(smem + OFF_BSM);

    for (;;) {
        if (tid == 0) {
            int tile = (int)atomicAdd(&g_tilectr, 1u);
            int rel = -1, start = 0, cnt = 0;
            if (tile < ntiles) {
                rel = 0;
                while (stp[rel + 1] <= tile) rel++;
                start = (tile - stp[rel]) * TM;
                cnt = min(TM, scnt[rel] - start);
            }
            ((int*)(smem + OFF_CTL))[0] = rel;
            ((int*)(smem + OFF_CTL))[1] = start;
            ((int*)(smem + OFF_CTL))[2] = cnt;
        }
        __syncthreads();
        int rel   = ((int*)(smem + OFF_CTL))[0];
        int start = ((int*)(smem + OFF_CTL))[1];
        int cnt   = ((int*)(smem + OFF_CTL))[2];
        if (rel < 0) break;

        // ---- kick off B staging via cp.async (overlaps the entire gather phase) ----
        {
            const uint4* bsrc = g_bfrag + (size_t)rel * 4096;
            #pragma unroll
            for (int i = 0; i < 16; i++) {
                int e = tid + i * 256;
                asm volatile("cp.async.cg.shared.global [%0], [%1], 16;"
                             :: "r"(bsm_base + e * 16), "l"(bsrc + e) : "memory");
            }
            asm volatile("cp.async.commit_group;" ::: "memory");
        }

        if (tid < D) rsh[tid] = rel_emb[rel * D + tid];

        // warp-local bucket read: lanes 0-3 hold rows w*4..w*4+3
        int4 b4 = make_int4(0, 0, 0, 0);
        if (l < 4 && w * 4 + l < cnt)
            b4 = g_bucket4[rel * M_TOT + start + w * 4 + l];
        if (l < 4 && w * 4 + l < cnt) msh[w * 4 + l] = b4.x;

        // ---- gather + packed bf16 split + stage A (u at row m, v at row 32+m); 4 m/warp ----
        float sqa[4];
        #pragma unroll
        for (int it = 0; it < 4; it++) {
            int m = w * 4 + it;
            int hm = __shfl_sync(0xffffffffu, b4.y, it);
            int pm = __shfl_sync(0xffffffffu, b4.z, it);
            int nm = __shfl_sync(0xffffffffu, b4.w, it);
            char* puh = smem + OFF_AHI + m * ASTRIDE + 8 * l;
            char* pul = smem + OFF_ALO + m * ASTRIDE + 8 * l;
            char* pvh = smem + OFF_AHI + (TM + m) * ASTRIDE + 8 * l;
            char* pvl = smem + OFF_ALO + (TM + m) * ASTRIDE + 8 * l;
            float sq = 0.f;
            if (m < cnt) {
                float4 h4 = ((const float4*)(ent + (size_t)hm * D))[l];
                float4 p4 = ((const float4*)(ent + (size_t)pm * D))[l];
                float4 n4 = ((const float4*)(ent + (size_t)nm * D))[l];
                float u0 = h4.x - p4.x, u1 = h4.y - p4.y, u2 = h4.z - p4.z, u3 = h4.w - p4.w;
                float v0 = h4.x - n4.x, v1 = h4.y - n4.y, v2 = h4.z - n4.z, v3 = h4.w - n4.w;
                sq = h4.x*h4.x + h4.y*h4.y + h4.z*h4.z + h4.w*h4.w
                   + p4.x*p4.x + p4.y*p4.y + p4.z*p4.z + p4.w*p4.w
                   + n4.x*n4.x + n4.y*n4.y + n4.z*n4.z + n4.w*n4.w;
                uint32_t uh01, ul01, uh23, ul23, vh01, vl01, vh23, vl23;
                split2(u0, u1, uh01, ul01);
                split2(u2, u3, uh23, ul23);
                split2(v0, v1, vh01, vl01);
                split2(v2, v3, vh23, vl23);
                *(uint2*)puh = make_uint2(uh01, uh23);
                *(uint2*)pul = make_uint2(ul01, ul23);
                *(uint2*)pvh = make_uint2(vh01, vh23);
                *(uint2*)pvl = make_uint2(vl01, vl23);
            } else {
                uint2 z = make_uint2(0u, 0u);
                *(uint2*)puh = z; *(uint2*)pul = z;
                *(uint2*)pvh = z; *(uint2*)pvl = z;
            }
            sqa[it] = sq;
        }
        #pragma unroll
        for (int it = 0; it < 4; it++) {
            float s = sqa[it];
            #pragma unroll
            for (int o = 16; o; o >>= 1) s += __shfl_xor_sync(0xffffffffu, s, o);
            if (l == 0) regsh[w * 4 + it] = s;
        }
        asm volatile("cp.async.wait_group 0;" ::: "memory");
        __syncthreads();

        // ---- MMA: warp (g,p) computes rows 16g..16g+15, nt = 8p..8p+7 (3-pass split) ----
        const char* A0h = smem + OFF_AHI + (16 * g + gid) * ASTRIDE + 4 * tig;
        const char* A1h = A0h + 8 * ASTRIDE;
        const char* A0l = smem + OFF_ALO + (16 * g + gid) * ASTRIDE + 4 * tig;
        const char* A1l = A0l + 8 * ASTRIDE;
        const uint4* bsm = (const uint4*)(smem + OFF_BSM) + (8 * p) * 32 + l;

        float c[8][4];
        #pragma unroll
        for (int nt = 0; nt < 8; nt++)
            #pragma unroll
            for (int i = 0; i < 4; i++) c[nt][i] = 0.f;

        for (int ks = 0; ks < 8; ks++) {
            uint32_t ah0 = *(const uint32_t*)(A0h + 32 * ks);
            uint32_t ah1 = *(const uint32_t*)(A1h + 32 * ks);
            uint32_t ah2 = *(const uint32_t*)(A0h + 32 * ks + 16);
            uint32_t ah3 = *(const uint32_t*)(A1h + 32 * ks + 16);
            uint32_t al0 = *(const uint32_t*)(A0l + 32 * ks);
            uint32_t al1 = *(const uint32_t*)(A1l + 32 * ks);
            uint32_t al2 = *(const uint32_t*)(A0l + 32 * ks + 16);
            uint32_t al3 = *(const uint32_t*)(A1l + 32 * ks + 16);

            const uint4* bp = bsm + (size_t)ks * 512;
            uint4 bb[8];
            #pragma unroll
            for (int nt = 0; nt < 8; nt++) bb[nt] = bp[nt * 32];   // LDS.128 conflict-free

            #pragma unroll
            for (int nt = 0; nt < 8; nt++) {
                mma_bf16(c[nt], ah0, ah1, ah2, ah3, bb[nt].x, bb[nt].y);
                mma_bf16(c[nt], ah0, ah1, ah2, ah3, bb[nt].z, bb[nt].w);
                mma_bf16(c[nt], al0, al1, al2, al3, bb[nt].x, bb[nt].y);
            }
        }

        // ---- epilogue: add r_j, square, reduce over this warp's 64 j's ----
        float sA = 0.f, sB = 0.f;        // rows 16g+gid, 16g+8+gid
        #pragma unroll
        for (int i = 0; i < 8; i++) {
            int nt = 8 * p + i;
            float r0 = rsh[8 * nt + 2 * tig];
            float r1 = rsh[8 * nt + 2 * tig + 1];
            float d0 = c[i][0] + r0, d1 = c[i][1] + r1;
            float d2 = c[i][2] + r0, d3 = c[i][3] + r1;
            sA += d0 * d0 + d1 * d1;
            sB += d2 * d2 + d3 * d3;
        }
        sA += __shfl_xor_sync(0xffffffffu, sA, 1);
        sA += __shfl_xor_sync(0xffffffffu, sA, 2);
        sB += __shfl_xor_sync(0xffffffffu, sB, 1);
        sB += __shfl_xor_sync(0xffffffffu, sB, 2);
        if (tig == 0) {
            sc[p * 64 + 16 * g + gid]     = sA;
            sc[p * 64 + 16 * g + 8 + gid] = sB;
        }
        __syncthreads();

        if (tid < TM && tid < cnt) {
            float pos = sc[tid]      + sc[64 + tid];        // u row: both j-halves
            float neg = sc[TM + tid] + sc[64 + TM + tid];   // v row
            float x = 0.5f * (pos - neg);
            float loss = fmaxf(-x, 0.f) + log1pf(expf(-fabsf(x)));  // softplus(-x)
            g_val[msh[tid]] = loss + REG_LAMBDA * 0.5f * (regsh[tid] + g_rsq[rel]);
        }
        __syncthreads();
    }

    // ---------- last-block deterministic reduction + state reset ----------
    __shared__ bool amLast;
    __threadfence();
    __syncthreads();
    if (tid == 0) {
        unsigned int prev = atomicAdd(&g_done, 1u);
        amLast = (prev == (unsigned int)(gridDim.x - 1));
    }
    __syncthreads();
    if (!amLast) return;
    __threadfence();

    double* sd = (double*)smem;
    double acc = 0.0;
    for (int i = tid; i < M_TOT; i += THREADS) acc += (double)g_val[i];
    sd[tid] = acc;
    __syncthreads();
    for (int s = THREADS / 2; s; s >>= 1) {
        if (tid < s) sd[tid] += sd[tid + s];
        __syncthreads();
    }
    if (tid == 0) out[0] = (float)(sd[0] / (double)M_TOT);

    if (tid < NREL) g_cnt[tid] = 0;
    if (tid == 0) { g_done = 0; g_bar = 0; g_tilectr = 0; }
}

// ---------------- launch ----------------
extern "C" void kernel_launch(void* const* d_in, const int* in_sizes, int n_in,
                              void* d_out, int out_size) {
    const int*   h       = (const int*)d_in[0];
    const int*   r       = (const int*)d_in[1];
    const int*   pos_t   = (const int*)d_in[2];
    const int*   neg_t   = (const int*)d_in[3];
    const float* ent     = (const float*)d_in[4];
    const float* rel_emb = (const float*)d_in[5];
    const float* rel_w   = (const float*)d_in[6];
    float* out = (float*)d_out;

    cudaFuncSetAttribute(k_all, cudaFuncAttributeMaxDynamicSharedMemorySize, SMEM_SZ);
    k_all<<<NBLK, THREADS, SMEM_SZ>>>(r, h, pos_t, neg_t, ent, rel_emb, rel_w, out);
}

// round 17
// speedup vs baseline: 1.0816x; 1.0816x over previous
#include <cuda_runtime.h>
#include <cuda_bf16.h>
#include <math.h>
#include <stdint.h>

// Fixed problem shapes
#define M_TOT 8192
#define NREL  64
#define D     128
#define TM    32            // m per tile -> 64 A rows (u rows 0..31, v rows 32..63)
#define THREADS 256
#define NBLK  296           // 2 blocks/SM x 148 SMs, all resident -> safe grid barrier
#define MAXT  320           // ntiles <= 8192/32 + 64
#define REG_LAMBDA 1e-5f

// ---------------- device scratch (zero-init at load; reset at end of each call) ----------------
__device__ int   g_cnt[NREL];
__device__ int4  g_bucket4[NREL * M_TOT];    // {m, h[m], pos[m], neg[m]}
__device__ float g_rsq[NREL];
__device__ float g_val[M_TOT];
__device__ unsigned int g_done;
__device__ unsigned int g_bar;
// B fragments in mma.m16n8k16 register layout:
// g_bfrag[rel*4096 + ks*512 + nt*32 + lane] = {b0_hi, b1_hi, b0_lo, b1_lo}
__device__ uint4 g_bfrag[NREL * 8 * 16 * 32];

// ---------------- helpers ----------------
// packed 2-value bf16 split (rn rounding)
static __device__ __forceinline__ void split2(float x0, float x1, uint32_t& hi, uint32_t& lo) {
    asm("cvt.rn.bf16x2.f32 %0, %1, %2;" : "=r"(hi) : "f"(x1), "f"(x0));
    float h0 = __uint_as_float(hi << 16);
    float h1 = __uint_as_float(hi & 0xffff0000u);
    float l0 = x0 - h0;
    float l1 = x1 - h1;
    asm("cvt.rn.bf16x2.f32 %0, %1, %2;" : "=r"(lo) : "f"(l1), "f"(l0));
}

static __device__ __forceinline__ void mma_bf16(float c[4],
                                                uint32_t a0, uint32_t a1,
                                                uint32_t a2, uint32_t a3,
                                                uint32_t b0, uint32_t b1) {
    asm("mma.sync.aligned.m16n8k16.row.col.f32.bf16.bf16.f32 "
        "{%0,%1,%2,%3}, {%4,%5,%6,%7}, {%8,%9}, {%0,%1,%2,%3};"
        : "+f"(c[0]), "+f"(c[1]), "+f"(c[2]), "+f"(c[3])
        : "r"(a0), "r"(a1), "r"(a2), "r"(a3), "r"(b0), "r"(b1));
}

// ---------------- smem layout (dynamic ~100 KB) ----------------
#define ASTRIDE 264
#define OFF_AHI 0                          // 64 * 264 = 16896
#define OFF_ALO 16896                      // -> 33792
#define OFF_BSM 33792                      // 65536 B of B fragments -> 99328
#define OFF_RSH 99328                      // 512
#define OFF_SC  99840                      // 512 (128 floats: [p*64 + row])
#define OFF_REG 100352                     // 128 (32 floats)
#define OFF_MSH 100480                     // 128
#define OFF_SCNT 100608                    // 256
#define OFF_STP  100864                    // 65 ints -> 101124
#define OFF_TMAP 101136                    // 320 shorts = 640 -> 101776
#define SMEM_SZ  101888

__global__ void __launch_bounds__(THREADS, 2) k_all(
    const int*   __restrict__ r,
    const int*   __restrict__ h,
    const int*   __restrict__ pos_t,
    const int*   __restrict__ neg_t,
    const float* __restrict__ ent,
    const float* __restrict__ rel_emb,
    const float* __restrict__ rel_w,
    float*       __restrict__ out)
{
    extern __shared__ char smem[];
    int b   = blockIdx.x;
    int tid = threadIdx.x;
    int w = tid >> 5, l = tid & 31;
    int g = w >> 1, p = w & 1;           // warp pair (rows), j-half
    int gid = l >> 2, tig = l & 3;

    // ================= Phase 1: scatter (blocks 0-31) / W fragments (32-159) =================
    if (b < 32) {
        int* scnt  = (int*)smem;
        int* sbase = scnt + NREL;
        int* scur  = sbase + NREL;
        if (tid < NREL) { scnt[tid] = 0; scur[tid] = 0; }
        __syncthreads();
        int m  = b * 256 + tid;
        int rl = r[m];
        int hm = h[m], pm = pos_t[m], nm = neg_t[m];
        atomicAdd(&scnt[rl], 1);
        __syncthreads();
        if (tid < NREL && scnt[tid] > 0) sbase[tid] = atomicAdd(&g_cnt[tid], scnt[tid]);
        __syncthreads();
        int pp = sbase[rl] + atomicAdd(&scur[rl], 1);
        g_bucket4[rl * M_TOT + pp] = make_int4(m, hm, pm, nm);
        if (b == 0) {
            for (int rel = w; rel < NREL; rel += 8) {
                const float4* re = (const float4*)(rel_emb + rel * D);
                float4 v = re[l];
                float s = v.x * v.x + v.y * v.y + v.z * v.z + v.w * v.w;
                #pragma unroll
                for (int o = 16; o; o >>= 1) s += __shfl_xor_sync(0xffffffffu, s, o);
                if (l == 0) g_rsq[rel] = s;
            }
        }
    } else if (b < 160) {
        // half-rel builder: 128 blocks, 32 KB stage (rows 64*half .. 64*half+63)
        int idx  = b - 32;
        int rel  = idx >> 1;
        int half = idx & 1;
        float* Wsh = (float*)smem;          // 64 x 128 f32 = 32 KB
        const float4* src = (const float4*)(rel_w + (size_t)rel * D * D + (size_t)(64 * half) * D);
        float4* dst = (float4*)Wsh;
        #pragma unroll
        for (int i = tid; i < 64 * D / 4; i += 256) dst[i] = src[i];   // coalesced
        __syncthreads();
        #pragma unroll
        for (int q = 0; q < 8; q++) {
            int e = half * 2048 + q * 256 + tid;   // global entry index within rel
            int lane = e & 31;
            int nt   = (e >> 5) & 15;
            int ks   = e >> 9;
            int gg = lane >> 2, tt = lane & 3;
            int j  = 8 * nt + gg;
            int lr = 16 * ks + 2 * tt - 64 * half; // local staged row
            uint32_t xh, xl, yh, yl;
            split2(Wsh[lr * D + j], Wsh[(lr + 1) * D + j], xh, xl);
            split2(Wsh[(lr + 8) * D + j], Wsh[(lr + 9) * D + j], yh, yl);
            g_bfrag[(size_t)rel * 4096 + e] = make_uint4(xh, yh, xl, yl);
        }
    }

    // ================= Grid barrier (RED arrival + volatile poll) =================
    __threadfence();
    __syncthreads();
    if (tid == 0) {
        atomicAdd(&g_bar, 1u);             // return unused -> RED (no serialization)
        while (*(volatile unsigned int*)&g_bar < NBLK) __nanosleep(32);
    }
    __syncthreads();

    // ================= Phase 2: per-block plan + static tiles =================
    float* rsh   = (float*)(smem + OFF_RSH);
    float* sc    = (float*)(smem + OFF_SC);
    float* regsh = (float*)(smem + OFF_REG);
    int*   msh   = (int*)(smem + OFF_MSH);
    int*   scnt  = (int*)(smem + OFF_SCNT);
    int*   stp   = (int*)(smem + OFF_STP);
    short* tmap  = (short*)(smem + OFF_TMAP);

    if (tid < NREL) scnt[tid] = g_cnt[tid];
    __syncthreads();
    if (w == 0) {
        // warp-parallel tile-offset scan: lane l covers rels 2l, 2l+1
        int a0 = (scnt[2 * l] + TM - 1) / TM;
        int a1 = (scnt[2 * l + 1] + TM - 1) / TM;
        int s  = a0 + a1;
        int sum = s;
        #pragma unroll
        for (int off = 1; off < 32; off <<= 1) {
            int t = __shfl_up_sync(0xffffffffu, sum, off);
            if (l >= off) sum += t;
        }
        int excl = sum - s;
        stp[2 * l]     = excl;
        stp[2 * l + 1] = excl + a0;
        if (l == 31) stp[NREL] = sum;
    }
    __syncthreads();
    int ntiles = stp[NREL];
    // parallel tile -> rel map (<= 320 entries)
    if (tid < NREL) {
        int e0 = stp[tid], e1 = stp[tid + 1];
        for (int t = e0; t < e1; t++) tmap[t] = (short)tid;
    }
    __syncthreads();

    uint32_t bsm_base = (uint32_t)__cvta_generic_to_shared(smem + OFF_BSM);

    #pragma unroll 1
    for (int pass = 0; pass < 2; pass++) {
        int tile = b + pass * NBLK;        // static assignment: no atomic claim
        int rel = -1, start = 0, cnt = 0;
        if (tile < ntiles) {
            rel   = tmap[tile];
            start = (tile - stp[rel]) * TM;
            cnt   = min(TM, scnt[rel] - start);
        }
        if (rel < 0) break;

        // ---- kick off B staging via cp.async (overlaps the gather phase) ----
        {
            const uint4* bsrc = g_bfrag + (size_t)rel * 4096;
            #pragma unroll
            for (int i = 0; i < 16; i++) {
                int e = tid + i * 256;
                asm volatile("cp.async.cg.shared.global [%0], [%1], 16;"
                             :: "r"(bsm_base + e * 16), "l"(bsrc + e) : "memory");
            }
            asm volatile("cp.async.commit_group;" ::: "memory");
        }

        if (tid < D) rsh[tid] = rel_emb[rel * D + tid];

        // warp-local bucket read: lanes 0-3 hold rows w*4..w*4+3
        int4 b4 = make_int4(0, 0, 0, 0);
        if (l < 4 && w * 4 + l < cnt)
            b4 = g_bucket4[rel * M_TOT + start + w * 4 + l];
        if (l < 4 && w * 4 + l < cnt) msh[w * 4 + l] = b4.x;

        // ---- gather + packed bf16 split + stage A (u at row m, v at row 32+m); 4 m/warp ----
        float sqa[4];
        #pragma unroll
        for (int it = 0; it < 4; it++) {
            int m = w * 4 + it;
            int hm = __shfl_sync(0xffffffffu, b4.y, it);
            int pm = __shfl_sync(0xffffffffu, b4.z, it);
            int nm = __shfl_sync(0xffffffffu, b4.w, it);
            char* puh = smem + OFF_AHI + m * ASTRIDE + 8 * l;
            char* pul = smem + OFF_ALO + m * ASTRIDE + 8 * l;
            char* pvh = smem + OFF_AHI + (TM + m) * ASTRIDE + 8 * l;
            char* pvl = smem + OFF_ALO + (TM + m) * ASTRIDE + 8 * l;
            float sq = 0.f;
            if (m < cnt) {
                float4 h4 = ((const float4*)(ent + (size_t)hm * D))[l];
                float4 p4 = ((const float4*)(ent + (size_t)pm * D))[l];
                float4 n4 = ((const float4*)(ent + (size_t)nm * D))[l];
                float u0 = h4.x - p4.x, u1 = h4.y - p4.y, u2 = h4.z - p4.z, u3 = h4.w - p4.w;
                float v0 = h4.x - n4.x, v1 = h4.y - n4.y, v2 = h4.z - n4.z, v3 = h4.w - n4.w;
                sq = h4.x*h4.x + h4.y*h4.y + h4.z*h4.z + h4.w*h4.w
                   + p4.x*p4.x + p4.y*p4.y + p4.z*p4.z + p4.w*p4.w
                   + n4.x*n4.x + n4.y*n4.y + n4.z*n4.z + n4.w*n4.w;
                uint32_t uh01, ul01, uh23, ul23, vh01, vl01, vh23, vl23;
                split2(u0, u1, uh01, ul01);
                split2(u2, u3, uh23, ul23);
                split2(v0, v1, vh01, vl01);
                split2(v2, v3, vh23, vl23);
                *(uint2*)puh = make_uint2(uh01, uh23);
                *(uint2*)pul = make_uint2(ul01, ul23);
                *(uint2*)pvh = make_uint2(vh01, vh23);
                *(uint2*)pvl = make_uint2(vl01, vl23);
            } else {
                uint2 z = make_uint2(0u, 0u);
                *(uint2*)puh = z; *(uint2*)pul = z;
                *(uint2*)pvh = z; *(uint2*)pvl = z;
            }
            sqa[it] = sq;
        }
        #pragma unroll
        for (int it = 0; it < 4; it++) {
            float s = sqa[it];
            #pragma unroll
            for (int o = 16; o; o >>= 1) s += __shfl_xor_sync(0xffffffffu, s, o);
            if (l == 0) regsh[w * 4 + it] = s;
        }
        asm volatile("cp.async.wait_group 0;" ::: "memory");
        __syncthreads();

        // ---- MMA: warp (g,p) computes rows 16g..16g+15, nt = 8p..8p+7 (3-pass split) ----
        const char* A0h = smem + OFF_AHI + (16 * g + gid) * ASTRIDE + 4 * tig;
        const char* A1h = A0h + 8 * ASTRIDE;
        const char* A0l = smem + OFF_ALO + (16 * g + gid) * ASTRIDE + 4 * tig;
        const char* A1l = A0l + 8 * ASTRIDE;
        const uint4* bsm = (const uint4*)(smem + OFF_BSM) + (8 * p) * 32 + l;

        float c[8][4];
        #pragma unroll
        for (int nt = 0; nt < 8; nt++)
            #pragma unroll
            for (int i = 0; i < 4; i++) c[nt][i] = 0.f;

        for (int ks = 0; ks < 8; ks++) {
            uint32_t ah0 = *(const uint32_t*)(A0h + 32 * ks);
            uint32_t ah1 = *(const uint32_t*)(A1h + 32 * ks);
            uint32_t ah2 = *(const uint32_t*)(A0h + 32 * ks + 16);
            uint32_t ah3 = *(const uint32_t*)(A1h + 32 * ks + 16);
            uint32_t al0 = *(const uint32_t*)(A0l + 32 * ks);
            uint32_t al1 = *(const uint32_t*)(A1l + 32 * ks);
            uint32_t al2 = *(const uint32_t*)(A0l + 32 * ks + 16);
            uint32_t al3 = *(const uint32_t*)(A1l + 32 * ks + 16);

            const uint4* bp = bsm + (size_t)ks * 512;
            uint4 bb[8];
            #pragma unroll
            for (int nt = 0; nt < 8; nt++) bb[nt] = bp[nt * 32];   // LDS.128 conflict-free

            #pragma unroll
            for (int nt = 0; nt < 8; nt++) {
                mma_bf16(c[nt], ah0, ah1, ah2, ah3, bb[nt].x, bb[nt].y);
                mma_bf16(c[nt], ah0, ah1, ah2, ah3, bb[nt].z, bb[nt].w);
                mma_bf16(c[nt], al0, al1, al2, al3, bb[nt].x, bb[nt].y);
            }
        }

        // ---- epilogue: add r_j, square, reduce over this warp's 64 j's ----
        float sA = 0.f, sB = 0.f;        // rows 16g+gid, 16g+8+gid
        #pragma unroll
        for (int i = 0; i < 8; i++) {
            int nt = 8 * p + i;
            float r0 = rsh[8 * nt + 2 * tig];
            float r1 = rsh[8 * nt + 2 * tig + 1];
            float d0 = c[i][0] + r0, d1 = c[i][1] + r1;
            float d2 = c[i][2] + r0, d3 = c[i][3] + r1;
            sA += d0 * d0 + d1 * d1;
            sB += d2 * d2 + d3 * d3;
        }
        sA += __shfl_xor_sync(0xffffffffu, sA, 1);
        sA += __shfl_xor_sync(0xffffffffu, sA, 2);
        sB += __shfl_xor_sync(0xffffffffu, sB, 1);
        sB += __shfl_xor_sync(0xffffffffu, sB, 2);
        if (tig == 0) {
            sc[p * 64 + 16 * g + gid]     = sA;
            sc[p * 64 + 16 * g + 8 + gid] = sB;
        }
        __syncthreads();

        if (tid < TM && tid < cnt) {
            float pos = sc[tid]      + sc[64 + tid];        // u row: both j-halves
            float neg = sc[TM + tid] + sc[64 + TM + tid];   // v row
            float x = 0.5f * (pos - neg);
            float loss = fmaxf(-x, 0.f) + log1pf(expf(-fabsf(x)));  // softplus(-x)
            g_val[msh[tid]] = loss + REG_LAMBDA * 0.5f * (regsh[tid] + g_rsq[rel]);
        }
        __syncthreads();
    }

    // ---------- RED arrival; block 0 polls and reduces (deterministic order) ----------
    __threadfence();
    __syncthreads();
    if (tid == 0) atomicAdd(&g_done, 1u);   // return unused -> RED
    if (b != 0) return;
    if (tid == 0) {
        while (*(volatile unsigned int*)&g_done < NBLK) __nanosleep(32);
    }
    __syncthreads();
    __threadfence();

    double* sd = (double*)smem;
    double acc = 0.0;
    for (int i = tid; i < M_TOT; i += THREADS) acc += (double)g_val[i];
    sd[tid] = acc;
    __syncthreads();
    for (int s = THREADS / 2; s; s >>= 1) {
        if (tid < s) sd[tid] += sd[tid + s];
        __syncthreads();
    }
    if (tid == 0) out[0] = (float)(sd[0] / (double)M_TOT);

    if (tid < NREL) g_cnt[tid] = 0;
    if (tid == 0) { g_done = 0; g_bar = 0; }
}

// ---------------- launch ----------------
extern "C" void kernel_launch(void* const* d_in, const int* in_sizes, int n_in,
                              void* d_out, int out_size) {
    const int*   h       = (const int*)d_in[0];
    const int*   r       = (const int*)d_in[1];
    const int*   pos_t   = (const int*)d_in[2];
    const int*   neg_t   = (const int*)d_in[3];
    const float* ent     = (const float*)d_in[4];
    const float* rel_emb = (const float*)d_in[5];
    const float* rel_w   = (const float*)d_in[6];
    float* out = (float*)d_out;

    cudaFuncSetAttribute(k_all, cudaFuncAttributeMaxDynamicSharedMemorySize, SMEM_SZ);
    k_all<<<NBLK, THREADS, SMEM_SZ>>>(r, h, pos_t, neg_t, ent, rel_emb, rel_w, out);
}